// round 9
// baseline (speedup 1.0000x reference)
#include <cuda_runtime.h>
#include <math.h>

#define B_      8
#define TNEW    512
#define DMODEL  1024
#define H_      16
#define DH      64
#define CACHED  2048
#define TTOTAL  2560
#define MROWS   (B_*TNEW)      // 4096
#define QKVN    3072

#define OFF_K   (MROWS*DMODEL)               // 4194304
#define OFF_V   (OFF_K + B_*H_*TTOTAL*DH)    // 25165824
#define OFF_LEN (OFF_V + B_*H_*TTOTAL*DH)    // 46137344

// Scratch (allocation-free rule: __device__ globals)
__device__ float g_qkv[MROWS*QKVN];        // raw q|k|v projections [4096][3072]
__device__ float g_q  [B_*H_*TNEW*DH];     // roped q (tf32 values), [BH][T][DH]
__device__ float g_kt [B_*H_*TTOTAL*DH];   // tf32 copy of k_total
__device__ float g_vt [B_*H_*TTOTAL*DH];   // tf32 copy of v_total
__device__ float g_ctx[MROWS*DMODEL];      // attention context [4096][1024]
__device__ int   g_counts[B_];
__device__ int   g_totals[B_];

// ---------------------------------------------------------------------------
// tf32 / cp.async helpers
// ---------------------------------------------------------------------------
__device__ __forceinline__ float t32(float f) {
    unsigned u;
    asm("cvt.rna.tf32.f32 %0, %1;" : "=r"(u) : "f"(f));
    return __uint_as_float(u);
}
__device__ __forceinline__ unsigned U(float f) { return __float_as_uint(f); }

__device__ __forceinline__ void mma8(float* c, const unsigned* a, const unsigned* b) {
    asm volatile(
        "mma.sync.aligned.m16n8k8.row.col.f32.tf32.tf32.f32 "
        "{%0,%1,%2,%3},{%4,%5,%6,%7},{%8,%9},{%0,%1,%2,%3};"
        : "+f"(c[0]), "+f"(c[1]), "+f"(c[2]), "+f"(c[3])
        : "r"(a[0]), "r"(a[1]), "r"(a[2]), "r"(a[3]), "r"(b[0]), "r"(b[1]));
}

__device__ __forceinline__ void cpa16(float* smem, const float* g) {
    unsigned s = (unsigned)__cvta_generic_to_shared(smem);
    asm volatile("cp.async.cg.shared.global [%0], [%1], 16;" :: "r"(s), "l"(g));
}
__device__ __forceinline__ void cpa_commit() { asm volatile("cp.async.commit_group;"); }
__device__ __forceinline__ void cpa_wait1()  { asm volatile("cp.async.wait_group 1;"); }
__device__ __forceinline__ void cpa_wait0()  { asm volatile("cp.async.wait_group 0;"); }

// ---------------------------------------------------------------------------
// Kernel 1: derive new_counts from valid_new_mask (dtype-probed), totals
// ---------------------------------------------------------------------------
__global__ void k_setup(const unsigned char* __restrict__ mask,
                        const int* __restrict__ past_len,
                        float* __restrict__ out_len)
{
    int b = blockIdx.x;
    int lane = threadIdx.x;
    bool bytemode = (mask[7*TNEW + 1] != 0);
    int cnt = 0;
    for (int t = lane; t < TNEW; t += 32) {
        int nz;
        if (bytemode) nz = (mask[b*TNEW + t] != 0);
        else          nz = (((const int*)mask)[b*TNEW + t] != 0);
        cnt += nz;
    }
    #pragma unroll
    for (int o = 16; o; o >>= 1) cnt += __shfl_xor_sync(0xffffffffu, cnt, o);
    if (lane == 0) {
        g_counts[b] = cnt;
        int tot = past_len[b] + cnt;
        g_totals[b] = tot;
        out_len[b] = (float)tot;
    }
}

// ---------------------------------------------------------------------------
// Accurate RoPE angles (fp64 range reduction, fp32 sincos)
// ---------------------------------------------------------------------------
__device__ __forceinline__ void rope_sc(int pos, float fi, float& sn, float& cs)
{
    double f = (double)pos * (double)fi;
    double k = floor(f * 0.15915494309189535);
    float fr = (float)(f - k * 6.283185307179586);
    sincosf(fr, &sn, &cs);
}

// ---------------------------------------------------------------------------
// Kernel 2: QKV projection  C[4096][3072] = X @ W^T + b   (tf32 mma)
// Blocks whose 128 token-rows are all invalid exit immediately.
// ---------------------------------------------------------------------------
__global__ __launch_bounds__(256) void k_gemm_qkv(
    const float* __restrict__ X,
    const float* __restrict__ Wq, const float* __restrict__ Wk, const float* __restrict__ Wv,
    const float* __restrict__ bq, const float* __restrict__ bk, const float* __restrict__ bv)
{
    __shared__ float As[128][36];
    __shared__ float Bs[128][36];
    int bm = blockIdx.y * 128;
    if ((bm & 511) >= g_counts[bm >> 9]) return;

    int bn = blockIdx.x * 128;
    int seg = bn >> 10;
    const float* W    = (seg == 0) ? Wq : ((seg == 1) ? Wk : Wv);
    const float* bias = (seg == 0) ? bq : ((seg == 1) ? bk : bv);
    int nl = bn & 1023;
    int tid = threadIdx.x;
    int warp = tid >> 5, lane = tid & 31;
    int wm = warp >> 1, wn = warp & 1;
    int r0 = lane >> 2, c0 = lane & 3;

    float acc[2][8][4];
    #pragma unroll
    for (int mt = 0; mt < 2; mt++)
        #pragma unroll
        for (int nt = 0; nt < 8; nt++)
            #pragma unroll
            for (int r = 0; r < 4; r++) acc[mt][nt][r] = 0.f;

    int lrow = tid >> 3;
    int lcol = (tid & 7) * 4;

    for (int k0 = 0; k0 < DMODEL; k0 += 32) {
        #pragma unroll
        for (int p = 0; p < 4; p++) {
            int row = p*32 + lrow;
            float4 a = *(const float4*)&X[(size_t)(bm + row)*DMODEL + k0 + lcol];
            float4 w = *(const float4*)&W[(size_t)(nl + row)*DMODEL + k0 + lcol];
            As[row][lcol+0] = t32(a.x); As[row][lcol+1] = t32(a.y);
            As[row][lcol+2] = t32(a.z); As[row][lcol+3] = t32(a.w);
            Bs[row][lcol+0] = t32(w.x); Bs[row][lcol+1] = t32(w.y);
            Bs[row][lcol+2] = t32(w.z); Bs[row][lcol+3] = t32(w.w);
        }
        __syncthreads();
        #pragma unroll
        for (int ks = 0; ks < 4; ks++) {
            int kk = ks*8;
            unsigned a[2][4], b[8][2];
            #pragma unroll
            for (int mt = 0; mt < 2; mt++) {
                int mr = wm*32 + mt*16 + r0;
                a[mt][0] = U(As[mr  ][kk + c0]);
                a[mt][1] = U(As[mr+8][kk + c0]);
                a[mt][2] = U(As[mr  ][kk + 4 + c0]);
                a[mt][3] = U(As[mr+8][kk + 4 + c0]);
            }
            #pragma unroll
            for (int nt = 0; nt < 8; nt++) {
                int nr = wn*64 + nt*8 + r0;
                b[nt][0] = U(Bs[nr][kk + c0]);
                b[nt][1] = U(Bs[nr][kk + 4 + c0]);
            }
            #pragma unroll
            for (int mt = 0; mt < 2; mt++)
                #pragma unroll
                for (int nt = 0; nt < 8; nt++)
                    mma8(acc[mt][nt], a[mt], b[nt]);
        }
        __syncthreads();
    }
    #pragma unroll
    for (int mt = 0; mt < 2; mt++) {
        #pragma unroll
        for (int nt = 0; nt < 8; nt++) {
            int row = bm + wm*32 + mt*16 + r0;
            int col = bn + wn*64 + nt*8 + 2*c0;
            float bx = bias[col & 1023], by = bias[(col+1) & 1023];
            float2 v0 = { acc[mt][nt][0] + bx, acc[mt][nt][1] + by };
            float2 v1 = { acc[mt][nt][2] + bx, acc[mt][nt][3] + by };
            *(float2*)&g_qkv[(size_t)row*QKVN + col]     = v0;
            *(float2*)&g_qkv[(size_t)(row+8)*QKVN + col] = v1;
        }
    }
}

// ---------------------------------------------------------------------------
// Kernel 3 (fused): assemble k_total/v_total (exact fp32 to d_out, tf32 copy
// to g_kt/g_vt) + RoPE on q (tf32 into g_q).
// ---------------------------------------------------------------------------
__global__ __launch_bounds__(256) void k_prep(
    const float* __restrict__ pastk, const float* __restrict__ pastv,
    const float* __restrict__ invf, const int* __restrict__ past_len,
    float* __restrict__ out)
{
    int bh = blockIdx.y; int b = bh >> 4; int h = bh & 15;
    int gid = blockIdx.x * 256 + threadIdx.x;
    int i = gid & 31; int s = gid >> 5;
    int pl = past_len[b]; int tot = g_totals[b]; int cnt = g_counts[b];
    float k0, k1, v0, v1;
    if (s < pl) {
        size_t base = ((size_t)bh*CACHED + s) * DH;
        k0 = pastk[base + i]; k1 = pastk[base + i + 32];
        v0 = pastv[base + i]; v1 = pastv[base + i + 32];
    } else if (s < tot) {
        int t = s - pl;
        size_t m = (size_t)(b*TNEW + t) * QKVN;
        float sn, cs; rope_sc(s, invf[i], sn, cs);
        float x0 = g_qkv[m + 1024 + h*DH + i];
        float x1 = g_qkv[m + 1024 + h*DH + i + 32];
        k0 = x0*cs - x1*sn;
        k1 = x1*cs + x0*sn;
        v0 = g_qkv[m + 2048 + h*DH + i];
        v1 = g_qkv[m + 2048 + h*DH + i + 32];
    } else {
        k0 = k1 = v0 = v1 = 0.f;
    }
    size_t base = ((size_t)bh*TTOTAL + s) * DH;
    out[OFF_K + base + i]      = k0;
    out[OFF_K + base + i + 32] = k1;
    out[OFF_V + base + i]      = v0;
    out[OFF_V + base + i + 32] = v1;
    g_kt[base + i]      = t32(k0);
    g_kt[base + i + 32] = t32(k1);
    g_vt[base + i]      = t32(v0);
    g_vt[base + i + 32] = t32(v1);

    if (s < TNEW) {
        int t = s;
        float o0 = 0.f, o1 = 0.f;
        if (t < cnt) {
            int pos = pl + t;
            float sn, cs; rope_sc(pos, invf[i], sn, cs);
            size_t m = (size_t)(b*TNEW + t) * QKVN + h*DH;
            float x0 = g_qkv[m + i];
            float x1 = g_qkv[m + i + 32];
            o0 = t32(x0*cs - x1*sn);
            o1 = t32(x1*cs + x0*sn);
        }
        size_t qb = ((size_t)bh*TNEW + t) * DH;
        g_q[qb + i]      = o0;
        g_q[qb + i + 32] = o1;
    }
}

// ---------------------------------------------------------------------------
// Kernel 4: flash attention, tf32 mma. K double-buffered cp.async, V single-
// buffered. NO P smem buffer: the S->PV fragment transpose is done with
// intra-quad shuffles. smem = 3 KV tiles = 52.2KB -> 4 CTAs/SM (16 warps).
// ---------------------------------------------------------------------------
#define AT 68
#define KVTILE (64*AT)

__global__ __launch_bounds__(128, 4) void k_attn()
{
    extern __shared__ float sm[];
    float* Kb[2] = { sm, sm + KVTILE };
    float* Vs = sm + 2*KVTILE;

    int bh = blockIdx.x;
    int b = bh >> 4;
    int qb = blockIdx.y << 6;
    if (qb >= g_counts[b]) return;       // dead-work skip (masked downstream)

    int tid = threadIdx.x;
    int warp = tid >> 5, lane = tid & 31;
    int r0 = lane >> 2, c0 = lane & 3;
    int parity = c0 & 1;
    int srcA = (lane & 28) | (c0 >> 1);  // lane holding cols {2*(c0>>1), +1} = col c0
    int srcB = srcA + 2;                 // lane holding col c0+4

    int tot = g_totals[b];
    int nkb = (tot + 63) >> 6;
    const float* kbase = g_kt + (size_t)bh*TTOTAL*DH;
    const float* vbase = g_vt + (size_t)bh*TTOTAL*DH;

    int prow = tid >> 4;           // 0..7
    int pcol = (tid & 15) * 4;     // 0..60

    // prefetch K tile 0 into buffer 0
    #pragma unroll
    for (int j = 0; j < 8; j++) {
        int row = j*8 + prow;
        cpa16(&Kb[0][row*AT + pcol], &kbase[(size_t)row*DH + pcol]);
    }
    cpa_commit();

    // Q fragments straight from gmem (values already tf32)
    unsigned qa[8][4];
    {
        const float* q0 = g_q + ((size_t)bh*TNEW + qb + warp*16 + r0) * DH;
        const float* q1 = q0 + 8*DH;
        #pragma unroll
        for (int ks = 0; ks < 8; ks++) {
            qa[ks][0] = U(q0[ks*8 + c0]);
            qa[ks][1] = U(q1[ks*8 + c0]);
            qa[ks][2] = U(q0[ks*8 + 4 + c0]);
            qa[ks][3] = U(q1[ks*8 + 4 + c0]);
        }
    }

    float oacc[8][4];
    #pragma unroll
    for (int nt = 0; nt < 8; nt++)
        #pragma unroll
        for (int r = 0; r < 4; r++) oacc[nt][r] = 0.f;
    float mrow0 = -1e30f, mrow1 = -1e30f, lrow0 = 0.f, lrow1 = 0.f;

    for (int kb = 0; kb < nkb; kb++) {
        cpa_wait0();          // K(kb) resident in Kb[kb&1]
        __syncthreads();      // prior iter's PV reads of Vs + S reads of Kb[nb] done

        // issue V(kb) now (consumed after softmax), then K(kb+1)
        {
            const float* vg = vbase + (size_t)kb*64*DH;
            #pragma unroll
            for (int j = 0; j < 8; j++) {
                int row = j*8 + prow;
                cpa16(&Vs[row*AT + pcol], &vg[(size_t)row*DH + pcol]);
            }
            cpa_commit();
        }
        bool havek = (kb + 1 < nkb);
        if (havek) {
            int nb = (kb + 1) & 1;
            const float* kg = kbase + (size_t)(kb+1)*64*DH;
            #pragma unroll
            for (int j = 0; j < 8; j++) {
                int row = j*8 + prow;
                cpa16(&Kb[nb][row*AT + pcol], &kg[(size_t)row*DH + pcol]);
            }
            cpa_commit();
        }

        const float* Ks = Kb[kb & 1];

        // S = Q K^T  (warp rows x 64 cols)
        float sacc[8][4];
        #pragma unroll
        for (int nt = 0; nt < 8; nt++)
            #pragma unroll
            for (int r = 0; r < 4; r++) sacc[nt][r] = 0.f;
        #pragma unroll
        for (int ks = 0; ks < 8; ks++) {
            #pragma unroll
            for (int nt = 0; nt < 8; nt++) {
                unsigned bb[2];
                bb[0] = U(Ks[(nt*8 + r0)*AT + ks*8 + c0]);
                bb[1] = U(Ks[(nt*8 + r0)*AT + ks*8 + 4 + c0]);
                mma8(sacc[nt], qa[ks], bb);
            }
        }

        // scale + mask + row max
        float ml0 = -1e30f, ml1 = -1e30f;
        #pragma unroll
        for (int nt = 0; nt < 8; nt++) {
            int col = kb*64 + nt*8 + 2*c0;
            bool v0 = col < tot, v1 = (col+1) < tot;
            float s0 = v0 ? sacc[nt][0]*0.125f : -1e30f;
            float s1 = v1 ? sacc[nt][1]*0.125f : -1e30f;
            float s2 = v0 ? sacc[nt][2]*0.125f : -1e30f;
            float s3 = v1 ? sacc[nt][3]*0.125f : -1e30f;
            sacc[nt][0] = s0; sacc[nt][1] = s1; sacc[nt][2] = s2; sacc[nt][3] = s3;
            ml0 = fmaxf(ml0, fmaxf(s0, s1));
            ml1 = fmaxf(ml1, fmaxf(s2, s3));
        }
        ml0 = fmaxf(ml0, __shfl_xor_sync(0xffffffffu, ml0, 1));
        ml0 = fmaxf(ml0, __shfl_xor_sync(0xffffffffu, ml0, 2));
        ml1 = fmaxf(ml1, __shfl_xor_sync(0xffffffffu, ml1, 1));
        ml1 = fmaxf(ml1, __shfl_xor_sync(0xffffffffu, ml1, 2));

        float mn0 = fmaxf(mrow0, ml0), mn1 = fmaxf(mrow1, ml1);
        float e0 = __expf(mrow0 - mn0), e1 = __expf(mrow1 - mn1);
        mrow0 = mn0; mrow1 = mn1;

        // P in registers: pr0 = row qr cols {2c0,2c0+1}, pr1 = row qr+8
        float pr0[8][2], pr1[8][2];
        float ls0 = 0.f, ls1 = 0.f;
        #pragma unroll
        for (int nt = 0; nt < 8; nt++) {
            float p0 = __expf(sacc[nt][0] - mn0);
            float p1 = __expf(sacc[nt][1] - mn0);
            float p2 = __expf(sacc[nt][2] - mn1);
            float p3 = __expf(sacc[nt][3] - mn1);
            ls0 += p0 + p1; ls1 += p2 + p3;
            pr0[nt][0] = t32(p0); pr0[nt][1] = t32(p1);
            pr1[nt][0] = t32(p2); pr1[nt][1] = t32(p3);
            oacc[nt][0] *= e0; oacc[nt][1] *= e0;
            oacc[nt][2] *= e1; oacc[nt][3] *= e1;
        }
        ls0 += __shfl_xor_sync(0xffffffffu, ls0, 1);
        ls0 += __shfl_xor_sync(0xffffffffu, ls0, 2);
        ls1 += __shfl_xor_sync(0xffffffffu, ls1, 1);
        ls1 += __shfl_xor_sync(0xffffffffu, ls1, 2);
        lrow0 = lrow0*e0 + ls0;
        lrow1 = lrow1*e1 + ls1;

        // V(kb) ready (leave K(kb+1) in flight when present)
        if (havek) cpa_wait1(); else cpa_wait0();
        __syncthreads();

        // O += P V ; P A-fragments via intra-quad shuffles
        #pragma unroll
        for (int ks = 0; ks < 8; ks++) {
            float a0 = __shfl_sync(0xffffffffu, pr0[ks][0], srcA);
            float b0 = __shfl_sync(0xffffffffu, pr0[ks][1], srcA);
            float a1 = __shfl_sync(0xffffffffu, pr1[ks][0], srcA);
            float b1 = __shfl_sync(0xffffffffu, pr1[ks][1], srcA);
            float a2 = __shfl_sync(0xffffffffu, pr0[ks][0], srcB);
            float b2 = __shfl_sync(0xffffffffu, pr0[ks][1], srcB);
            float a3 = __shfl_sync(0xffffffffu, pr1[ks][0], srcB);
            float b3 = __shfl_sync(0xffffffffu, pr1[ks][1], srcB);
            unsigned pa[4];
            pa[0] = U(parity ? b0 : a0);
            pa[1] = U(parity ? b1 : a1);
            pa[2] = U(parity ? b2 : a2);
            pa[3] = U(parity ? b3 : a3);
            #pragma unroll
            for (int nt = 0; nt < 8; nt++) {
                unsigned bb[2];
                bb[0] = U(Vs[(ks*8 + c0    )*AT + nt*8 + r0]);
                bb[1] = U(Vs[(ks*8 + 4 + c0)*AT + nt*8 + r0]);
                mma8(oacc[nt], pa, bb);
            }
        }
    }

    // finalize
    float inv0 = 1.f / lrow0, inv1 = 1.f / lrow1;
    float* op = g_ctx + ((size_t)b*TNEW + qb + warp*16) * DMODEL + (bh & 15)*DH;
    #pragma unroll
    for (int nt = 0; nt < 8; nt++) {
        int col = nt*8 + 2*c0;
        float2 v0 = { oacc[nt][0]*inv0, oacc[nt][1]*inv0 };
        float2 v1 = { oacc[nt][2]*inv1, oacc[nt][3]*inv1 };
        *(float2*)&op[(size_t)r0*DMODEL + col]       = v0;
        *(float2*)&op[(size_t)(r0+8)*DMODEL + col]   = v1;
    }
}

// ---------------------------------------------------------------------------
// Kernel 5: output projection + valid-token mask (tf32 mma)
// All-invalid blocks write exact zeros and exit.
// ---------------------------------------------------------------------------
__global__ __launch_bounds__(256) void k_gemm_out(
    const float* __restrict__ Wo, const float* __restrict__ bo,
    float* __restrict__ out)
{
    __shared__ float As[128][36];
    __shared__ float Bs[128][36];
    int bm = blockIdx.y * 128;
    int bn = blockIdx.x * 128;
    int tid = threadIdx.x;

    if ((bm & 511) >= g_counts[bm >> 9]) {
        float4 z = {0.f, 0.f, 0.f, 0.f};
        #pragma unroll
        for (int j = 0; j < 16; j++) {
            int id = j*256 + tid;
            int row = id >> 5;
            int col = (id & 31) * 4;
            *(float4*)&out[(size_t)(bm + row)*DMODEL + bn + col] = z;
        }
        return;
    }

    int warp = tid >> 5, lane = tid & 31;
    int wm = warp >> 1, wn = warp & 1;
    int r0 = lane >> 2, c0 = lane & 3;

    float acc[2][8][4];
    #pragma unroll
    for (int mt = 0; mt < 2; mt++)
        #pragma unroll
        for (int nt = 0; nt < 8; nt++)
            #pragma unroll
            for (int r = 0; r < 4; r++) acc[mt][nt][r] = 0.f;

    int lrow = tid >> 3;
    int lcol = (tid & 7) * 4;

    for (int k0 = 0; k0 < DMODEL; k0 += 32) {
        #pragma unroll
        for (int p = 0; p < 4; p++) {
            int row = p*32 + lrow;
            float4 a = *(const float4*)&g_ctx[(size_t)(bm + row)*DMODEL + k0 + lcol];
            float4 w = *(const float4*)&Wo[(size_t)(bn + row)*DMODEL + k0 + lcol];
            As[row][lcol+0] = t32(a.x); As[row][lcol+1] = t32(a.y);
            As[row][lcol+2] = t32(a.z); As[row][lcol+3] = t32(a.w);
            Bs[row][lcol+0] = t32(w.x); Bs[row][lcol+1] = t32(w.y);
            Bs[row][lcol+2] = t32(w.z); Bs[row][lcol+3] = t32(w.w);
        }
        __syncthreads();
        #pragma unroll
        for (int ks = 0; ks < 4; ks++) {
            int kk = ks*8;
            unsigned a[2][4], b[8][2];
            #pragma unroll
            for (int mt = 0; mt < 2; mt++) {
                int mr = wm*32 + mt*16 + r0;
                a[mt][0] = U(As[mr  ][kk + c0]);
                a[mt][1] = U(As[mr+8][kk + c0]);
                a[mt][2] = U(As[mr  ][kk + 4 + c0]);
                a[mt][3] = U(As[mr+8][kk + 4 + c0]);
            }
            #pragma unroll
            for (int nt = 0; nt < 8; nt++) {
                int nr = wn*64 + nt*8 + r0;
                b[nt][0] = U(Bs[nr][kk + c0]);
                b[nt][1] = U(Bs[nr][kk + 4 + c0]);
            }
            #pragma unroll
            for (int mt = 0; mt < 2; mt++)
                #pragma unroll
                for (int nt = 0; nt < 8; nt++)
                    mma8(acc[mt][nt], a[mt], b[nt]);
        }
        __syncthreads();
    }
    #pragma unroll
    for (int mt = 0; mt < 2; mt++) {
        int row = bm + wm*32 + mt*16 + r0;
        int bb0 = (row)     >> 9, tt0 = (row)     & 511;
        int bb1 = (row + 8) >> 9, tt1 = (row + 8) & 511;
        float m0 = (tt0 < g_counts[bb0]) ? 1.f : 0.f;
        float m1 = (tt1 < g_counts[bb1]) ? 1.f : 0.f;
        #pragma unroll
        for (int nt = 0; nt < 8; nt++) {
            int col = bn + wn*64 + nt*8 + 2*c0;
            float bx = bo[col], by = bo[col+1];
            float2 v0 = { (acc[mt][nt][0] + bx)*m0, (acc[mt][nt][1] + by)*m0 };
            float2 v1 = { (acc[mt][nt][2] + bx)*m1, (acc[mt][nt][3] + by)*m1 };
            *(float2*)&out[(size_t)row*DMODEL + col]     = v0;
            *(float2*)&out[(size_t)(row+8)*DMODEL + col] = v1;
        }
    }
}

// ---------------------------------------------------------------------------
extern "C" void kernel_launch(void* const* d_in, const int* in_sizes, int n_in,
                              void* d_out, int out_size)
{
    const float* x     = (const float*)d_in[0];
    const float* invf  = (const float*)d_in[1];
    const float* pastk = (const float*)d_in[2];
    const float* pastv = (const float*)d_in[3];
    const float* Wq    = (const float*)d_in[4];
    const float* bq    = (const float*)d_in[5];
    const float* Wk    = (const float*)d_in[6];
    const float* bk    = (const float*)d_in[7];
    const float* Wv    = (const float*)d_in[8];
    const float* bv    = (const float*)d_in[9];
    const float* Wo    = (const float*)d_in[10];
    const float* bo    = (const float*)d_in[11];
    const int* past_len = (const int*)d_in[13];
    const unsigned char* vmask = (const unsigned char*)d_in[14];
    float* out = (float*)d_out;

    k_setup<<<B_, 32>>>(vmask, past_len, out + OFF_LEN);
    k_gemm_qkv<<<dim3(QKVN/128, MROWS/128), 256>>>(x, Wq, Wk, Wv, bq, bk, bv);
    k_prep<<<dim3(TTOTAL*32/256, B_*H_), 256>>>(pastk, pastv, invf, past_len, out);

    int smem = 3*KVTILE*4;   // 52224 bytes -> 4 CTAs/SM
    cudaFuncSetAttribute(k_attn, cudaFuncAttributeMaxDynamicSharedMemorySize, smem);
    k_attn<<<dim3(B_*H_, TNEW/64), 128, smem>>>();

    k_gemm_out<<<dim3(DMODEL/128, MROWS/128), 256>>>(Wo, bo, out);
}

// round 10
// speedup vs baseline: 1.0952x; 1.0952x over previous
#include <cuda_runtime.h>
#include <math.h>

#define B_      8
#define TNEW    512
#define DMODEL  1024
#define H_      16
#define DH      64
#define CACHED  2048
#define TTOTAL  2560
#define MROWS   (B_*TNEW)      // 4096
#define QKVN    3072

#define OFF_K   (MROWS*DMODEL)               // 4194304
#define OFF_V   (OFF_K + B_*H_*TTOTAL*DH)    // 25165824
#define OFF_LEN (OFF_V + B_*H_*TTOTAL*DH)    // 46137344

// Scratch (allocation-free rule: __device__ globals)
__device__ float g_qkv[MROWS*QKVN];        // raw q|k|v projections [4096][3072]
__device__ float g_q  [B_*H_*TNEW*DH];     // roped q (tf32, pre-scaled by 1/8)
__device__ float g_kt [B_*H_*TTOTAL*DH];   // tf32 copy of k_total
__device__ float g_vt [B_*H_*TTOTAL*DH];   // tf32 copy of v_total
__device__ float g_ctx[MROWS*DMODEL];      // attention context [4096][1024]
__device__ int   g_counts[B_];
__device__ int   g_totals[B_];

// ---------------------------------------------------------------------------
// tf32 / cp.async helpers
// ---------------------------------------------------------------------------
__device__ __forceinline__ float t32(float f) {
    unsigned u;
    asm("cvt.rna.tf32.f32 %0, %1;" : "=r"(u) : "f"(f));
    return __uint_as_float(u);
}
__device__ __forceinline__ unsigned U(float f) { return __float_as_uint(f); }

__device__ __forceinline__ void mma8(float* c, const unsigned* a, const unsigned* b) {
    asm volatile(
        "mma.sync.aligned.m16n8k8.row.col.f32.tf32.tf32.f32 "
        "{%0,%1,%2,%3},{%4,%5,%6,%7},{%8,%9},{%0,%1,%2,%3};"
        : "+f"(c[0]), "+f"(c[1]), "+f"(c[2]), "+f"(c[3])
        : "r"(a[0]), "r"(a[1]), "r"(a[2]), "r"(a[3]), "r"(b[0]), "r"(b[1]));
}

__device__ __forceinline__ void cpa16(float* smem, const float* g) {
    unsigned s = (unsigned)__cvta_generic_to_shared(smem);
    asm volatile("cp.async.cg.shared.global [%0], [%1], 16;" :: "r"(s), "l"(g));
}
__device__ __forceinline__ void cpa_commit() { asm volatile("cp.async.commit_group;"); }
__device__ __forceinline__ void cpa_wait1()  { asm volatile("cp.async.wait_group 1;"); }
__device__ __forceinline__ void cpa_wait0()  { asm volatile("cp.async.wait_group 0;"); }

// ---------------------------------------------------------------------------
// Kernel 1: derive new_counts from valid_new_mask (dtype-probed), totals
// ---------------------------------------------------------------------------
__global__ void k_setup(const unsigned char* __restrict__ mask,
                        const int* __restrict__ past_len,
                        float* __restrict__ out_len)
{
    int b = blockIdx.x;
    int lane = threadIdx.x;
    bool bytemode = (mask[7*TNEW + 1] != 0);
    int cnt = 0;
    for (int t = lane; t < TNEW; t += 32) {
        int nz;
        if (bytemode) nz = (mask[b*TNEW + t] != 0);
        else          nz = (((const int*)mask)[b*TNEW + t] != 0);
        cnt += nz;
    }
    #pragma unroll
    for (int o = 16; o; o >>= 1) cnt += __shfl_xor_sync(0xffffffffu, cnt, o);
    if (lane == 0) {
        g_counts[b] = cnt;
        int tot = past_len[b] + cnt;
        g_totals[b] = tot;
        out_len[b] = (float)tot;
    }
}

// ---------------------------------------------------------------------------
// Accurate RoPE angles (fp64 range reduction, fp32 sincos)
// ---------------------------------------------------------------------------
__device__ __forceinline__ void rope_sc(int pos, float fi, float& sn, float& cs)
{
    double f = (double)pos * (double)fi;
    double k = floor(f * 0.15915494309189535);
    float fr = (float)(f - k * 6.283185307179586);
    sincosf(fr, &sn, &cs);
}

// ---------------------------------------------------------------------------
// Kernel 2: QKV projection  C[4096][3072] = X @ W^T + b   (tf32 mma)
// Blocks whose 128 token-rows are all invalid exit immediately.
// ---------------------------------------------------------------------------
__global__ __launch_bounds__(256) void k_gemm_qkv(
    const float* __restrict__ X,
    const float* __restrict__ Wq, const float* __restrict__ Wk, const float* __restrict__ Wv,
    const float* __restrict__ bq, const float* __restrict__ bk, const float* __restrict__ bv)
{
    __shared__ float As[128][36];
    __shared__ float Bs[128][36];
    int bm = blockIdx.y * 128;
    if ((bm & 511) >= g_counts[bm >> 9]) return;

    int bn = blockIdx.x * 128;
    int seg = bn >> 10;
    const float* W    = (seg == 0) ? Wq : ((seg == 1) ? Wk : Wv);
    const float* bias = (seg == 0) ? bq : ((seg == 1) ? bk : bv);
    int nl = bn & 1023;
    int tid = threadIdx.x;
    int warp = tid >> 5, lane = tid & 31;
    int wm = warp >> 1, wn = warp & 1;
    int r0 = lane >> 2, c0 = lane & 3;

    float acc[2][8][4];
    #pragma unroll
    for (int mt = 0; mt < 2; mt++)
        #pragma unroll
        for (int nt = 0; nt < 8; nt++)
            #pragma unroll
            for (int r = 0; r < 4; r++) acc[mt][nt][r] = 0.f;

    int lrow = tid >> 3;
    int lcol = (tid & 7) * 4;

    for (int k0 = 0; k0 < DMODEL; k0 += 32) {
        #pragma unroll
        for (int p = 0; p < 4; p++) {
            int row = p*32 + lrow;
            float4 a = *(const float4*)&X[(size_t)(bm + row)*DMODEL + k0 + lcol];
            float4 w = *(const float4*)&W[(size_t)(nl + row)*DMODEL + k0 + lcol];
            As[row][lcol+0] = t32(a.x); As[row][lcol+1] = t32(a.y);
            As[row][lcol+2] = t32(a.z); As[row][lcol+3] = t32(a.w);
            Bs[row][lcol+0] = t32(w.x); Bs[row][lcol+1] = t32(w.y);
            Bs[row][lcol+2] = t32(w.z); Bs[row][lcol+3] = t32(w.w);
        }
        __syncthreads();
        #pragma unroll
        for (int ks = 0; ks < 4; ks++) {
            int kk = ks*8;
            unsigned a[2][4], b[8][2];
            #pragma unroll
            for (int mt = 0; mt < 2; mt++) {
                int mr = wm*32 + mt*16 + r0;
                a[mt][0] = U(As[mr  ][kk + c0]);
                a[mt][1] = U(As[mr+8][kk + c0]);
                a[mt][2] = U(As[mr  ][kk + 4 + c0]);
                a[mt][3] = U(As[mr+8][kk + 4 + c0]);
            }
            #pragma unroll
            for (int nt = 0; nt < 8; nt++) {
                int nr = wn*64 + nt*8 + r0;
                b[nt][0] = U(Bs[nr][kk + c0]);
                b[nt][1] = U(Bs[nr][kk + 4 + c0]);
            }
            #pragma unroll
            for (int mt = 0; mt < 2; mt++)
                #pragma unroll
                for (int nt = 0; nt < 8; nt++)
                    mma8(acc[mt][nt], a[mt], b[nt]);
        }
        __syncthreads();
    }
    #pragma unroll
    for (int mt = 0; mt < 2; mt++) {
        #pragma unroll
        for (int nt = 0; nt < 8; nt++) {
            int row = bm + wm*32 + mt*16 + r0;
            int col = bn + wn*64 + nt*8 + 2*c0;
            float bx = bias[col & 1023], by = bias[(col+1) & 1023];
            float2 v0 = { acc[mt][nt][0] + bx, acc[mt][nt][1] + by };
            float2 v1 = { acc[mt][nt][2] + bx, acc[mt][nt][3] + by };
            *(float2*)&g_qkv[(size_t)row*QKVN + col]     = v0;
            *(float2*)&g_qkv[(size_t)(row+8)*QKVN + col] = v1;
        }
    }
}

// ---------------------------------------------------------------------------
// Kernel 3 (fused): assemble k_total/v_total (exact fp32 to d_out, tf32 copy
// to g_kt/g_vt) + RoPE on q (tf32, pre-scaled by 1/8, into g_q).
// ---------------------------------------------------------------------------
__global__ __launch_bounds__(256) void k_prep(
    const float* __restrict__ pastk, const float* __restrict__ pastv,
    const float* __restrict__ invf, const int* __restrict__ past_len,
    float* __restrict__ out)
{
    int bh = blockIdx.y; int b = bh >> 4; int h = bh & 15;
    int gid = blockIdx.x * 256 + threadIdx.x;
    int i = gid & 31; int s = gid >> 5;
    int pl = past_len[b]; int tot = g_totals[b]; int cnt = g_counts[b];
    float k0, k1, v0, v1;
    if (s < pl) {
        size_t base = ((size_t)bh*CACHED + s) * DH;
        k0 = pastk[base + i]; k1 = pastk[base + i + 32];
        v0 = pastv[base + i]; v1 = pastv[base + i + 32];
    } else if (s < tot) {
        int t = s - pl;
        size_t m = (size_t)(b*TNEW + t) * QKVN;
        float sn, cs; rope_sc(s, invf[i], sn, cs);
        float x0 = g_qkv[m + 1024 + h*DH + i];
        float x1 = g_qkv[m + 1024 + h*DH + i + 32];
        k0 = x0*cs - x1*sn;
        k1 = x1*cs + x0*sn;
        v0 = g_qkv[m + 2048 + h*DH + i];
        v1 = g_qkv[m + 2048 + h*DH + i + 32];
    } else {
        k0 = k1 = v0 = v1 = 0.f;
    }
    size_t base = ((size_t)bh*TTOTAL + s) * DH;
    out[OFF_K + base + i]      = k0;
    out[OFF_K + base + i + 32] = k1;
    out[OFF_V + base + i]      = v0;
    out[OFF_V + base + i + 32] = v1;
    g_kt[base + i]      = t32(k0);
    g_kt[base + i + 32] = t32(k1);
    g_vt[base + i]      = t32(v0);
    g_vt[base + i + 32] = t32(v1);

    if (s < TNEW) {
        int t = s;
        float o0 = 0.f, o1 = 0.f;
        if (t < cnt) {
            int pos = pl + t;
            float sn, cs; rope_sc(pos, invf[i], sn, cs);
            size_t m = (size_t)(b*TNEW + t) * QKVN + h*DH;
            float x0 = g_qkv[m + i];
            float x1 = g_qkv[m + i + 32];
            // fold 1/sqrt(DH)=0.125 (exact power of two) into q: bit-identical
            // to scaling S afterwards.
            o0 = t32(x0*cs - x1*sn) * 0.125f;
            o1 = t32(x1*cs + x0*sn) * 0.125f;
        }
        size_t qb = ((size_t)bh*TNEW + t) * DH;
        g_q[qb + i]      = o0;
        g_q[qb + i + 32] = o1;
    }
}

// ---------------------------------------------------------------------------
// Kernel 4: flash attention, tf32 mma (R8 geometry: Ps in smem, 3 CTAs/SM).
// K double-buffered cp.async, V single-buffered. Scale folded into q;
// column masking applied ONLY on the final k-tile.
// ---------------------------------------------------------------------------
#define AT 68
#define KVTILE (64*AT)

__global__ __launch_bounds__(128, 3) void k_attn()
{
    extern __shared__ float sm[];
    float* Kb[2] = { sm, sm + KVTILE };
    float* Vs = sm + 2*KVTILE;
    float (*Ps)[AT] = (float(*)[AT])(sm + 3*KVTILE);   // Q staging, then P

    int bh = blockIdx.x;
    int b = bh >> 4;
    int qb = blockIdx.y << 6;
    if (qb >= g_counts[b]) return;       // dead-work skip (masked downstream)

    int tid = threadIdx.x;
    int warp = tid >> 5, lane = tid & 31;
    int r0 = lane >> 2, c0 = lane & 3;

    int tot = g_totals[b];
    int nkb = (tot + 63) >> 6;
    const float* kbase = g_kt + (size_t)bh*TTOTAL*DH;
    const float* vbase = g_vt + (size_t)bh*TTOTAL*DH;

    int prow = tid >> 4;           // 0..7
    int pcol = (tid & 15) * 4;     // 0..60

    // prefetch K tile 0 into buffer 0
    #pragma unroll
    for (int j = 0; j < 8; j++) {
        int row = j*8 + prow;
        cpa16(&Kb[0][row*AT + pcol], &kbase[(size_t)row*DH + pcol]);
    }
    cpa_commit();

    // stage Q (64x64, already tf32+scaled) into Ps
    {
        const float* qp = g_q + ((size_t)bh*TNEW + qb) * DH;
        #pragma unroll
        for (int j = 0; j < 8; j++) {
            int id = j*128 + tid;
            int row = id >> 4;
            int c = (id & 15) * 4;
            *(float4*)&Ps[row][c] = *(const float4*)&qp[(size_t)row*DH + c];
        }
    }
    __syncthreads();

    // Q fragments (warp-local rows)
    unsigned qa[8][4];
    int qr = warp*16 + r0;
    #pragma unroll
    for (int ks = 0; ks < 8; ks++) {
        qa[ks][0] = U(Ps[qr  ][ks*8 + c0]);
        qa[ks][1] = U(Ps[qr+8][ks*8 + c0]);
        qa[ks][2] = U(Ps[qr  ][ks*8 + 4 + c0]);
        qa[ks][3] = U(Ps[qr+8][ks*8 + 4 + c0]);
    }

    float oacc[8][4];
    #pragma unroll
    for (int nt = 0; nt < 8; nt++)
        #pragma unroll
        for (int r = 0; r < 4; r++) oacc[nt][r] = 0.f;
    float mrow0 = -1e30f, mrow1 = -1e30f, lrow0 = 0.f, lrow1 = 0.f;

    for (int kb = 0; kb < nkb; kb++) {
        cpa_wait0();          // K(kb) resident in Kb[kb&1]
        __syncthreads();      // prior iter's PV reads of Vs/Ps complete (all warps)

        // issue V(kb) now (consumed after softmax), then K(kb+1)
        {
            const float* vg = vbase + (size_t)kb*64*DH;
            #pragma unroll
            for (int j = 0; j < 8; j++) {
                int row = j*8 + prow;
                cpa16(&Vs[row*AT + pcol], &vg[(size_t)row*DH + pcol]);
            }
            cpa_commit();
        }
        bool havek = (kb + 1 < nkb);
        if (havek) {
            int nb = (kb + 1) & 1;
            const float* kg = kbase + (size_t)(kb+1)*64*DH;
            #pragma unroll
            for (int j = 0; j < 8; j++) {
                int row = j*8 + prow;
                cpa16(&Kb[nb][row*AT + pcol], &kg[(size_t)row*DH + pcol]);
            }
            cpa_commit();
        }

        const float* Ks = Kb[kb & 1];

        // S = Q K^T  (warp rows x 64 cols); scale already folded into q
        float sacc[8][4];
        #pragma unroll
        for (int nt = 0; nt < 8; nt++)
            #pragma unroll
            for (int r = 0; r < 4; r++) sacc[nt][r] = 0.f;
        #pragma unroll
        for (int ks = 0; ks < 8; ks++) {
            #pragma unroll
            for (int nt = 0; nt < 8; nt++) {
                unsigned bb[2];
                bb[0] = U(Ks[(nt*8 + r0)*AT + ks*8 + c0]);
                bb[1] = U(Ks[(nt*8 + r0)*AT + ks*8 + 4 + c0]);
                mma8(sacc[nt], qa[ks], bb);
            }
        }

        // mask only on the final tile (all earlier tiles fully valid)
        if (kb == nkb - 1) {
            #pragma unroll
            for (int nt = 0; nt < 8; nt++) {
                int col = kb*64 + nt*8 + 2*c0;
                if (col     >= tot) { sacc[nt][0] = -1e30f; sacc[nt][2] = -1e30f; }
                if (col + 1 >= tot) { sacc[nt][1] = -1e30f; sacc[nt][3] = -1e30f; }
            }
        }

        // row max
        float ml0 = -1e30f, ml1 = -1e30f;
        #pragma unroll
        for (int nt = 0; nt < 8; nt++) {
            ml0 = fmaxf(ml0, fmaxf(sacc[nt][0], sacc[nt][1]));
            ml1 = fmaxf(ml1, fmaxf(sacc[nt][2], sacc[nt][3]));
        }
        ml0 = fmaxf(ml0, __shfl_xor_sync(0xffffffffu, ml0, 1));
        ml0 = fmaxf(ml0, __shfl_xor_sync(0xffffffffu, ml0, 2));
        ml1 = fmaxf(ml1, __shfl_xor_sync(0xffffffffu, ml1, 1));
        ml1 = fmaxf(ml1, __shfl_xor_sync(0xffffffffu, ml1, 2));

        float mn0 = fmaxf(mrow0, ml0), mn1 = fmaxf(mrow1, ml1);
        float e0 = __expf(mrow0 - mn0), e1 = __expf(mrow1 - mn1);
        mrow0 = mn0; mrow1 = mn1;

        float ls0 = 0.f, ls1 = 0.f;
        #pragma unroll
        for (int nt = 0; nt < 8; nt++) {
            float p0 = __expf(sacc[nt][0] - mn0);
            float p1 = __expf(sacc[nt][1] - mn0);
            float p2 = __expf(sacc[nt][2] - mn1);
            float p3 = __expf(sacc[nt][3] - mn1);
            ls0 += p0 + p1; ls1 += p2 + p3;
            float2 w0 = { t32(p0), t32(p1) };
            float2 w1 = { t32(p2), t32(p3) };
            *(float2*)&Ps[warp*16 + r0    ][nt*8 + 2*c0] = w0;
            *(float2*)&Ps[warp*16 + r0 + 8][nt*8 + 2*c0] = w1;
            oacc[nt][0] *= e0; oacc[nt][1] *= e0;
            oacc[nt][2] *= e1; oacc[nt][3] *= e1;
        }
        ls0 += __shfl_xor_sync(0xffffffffu, ls0, 1);
        ls0 += __shfl_xor_sync(0xffffffffu, ls0, 2);
        ls1 += __shfl_xor_sync(0xffffffffu, ls1, 1);
        ls1 += __shfl_xor_sync(0xffffffffu, ls1, 2);
        lrow0 = lrow0*e0 + ls0;
        lrow1 = lrow1*e1 + ls1;

        // V(kb) ready (leave K(kb+1) in flight when present)
        if (havek) cpa_wait1(); else cpa_wait0();
        __syncthreads();

        // O += P V  (P rows are warp-private)
        #pragma unroll
        for (int ks = 0; ks < 8; ks++) {
            unsigned pa[4];
            pa[0] = U(Ps[warp*16 + r0    ][ks*8 + c0]);
            pa[1] = U(Ps[warp*16 + r0 + 8][ks*8 + c0]);
            pa[2] = U(Ps[warp*16 + r0    ][ks*8 + 4 + c0]);
            pa[3] = U(Ps[warp*16 + r0 + 8][ks*8 + 4 + c0]);
            #pragma unroll
            for (int nt = 0; nt < 8; nt++) {
                unsigned bb[2];
                bb[0] = U(Vs[(ks*8 + c0    )*AT + nt*8 + r0]);
                bb[1] = U(Vs[(ks*8 + 4 + c0)*AT + nt*8 + r0]);
                mma8(oacc[nt], pa, bb);
            }
        }
    }

    // finalize
    float inv0 = 1.f / lrow0, inv1 = 1.f / lrow1;
    float* op = g_ctx + ((size_t)b*TNEW + qb + warp*16) * DMODEL + (bh & 15)*DH;
    #pragma unroll
    for (int nt = 0; nt < 8; nt++) {
        int col = nt*8 + 2*c0;
        float2 v0 = { oacc[nt][0]*inv0, oacc[nt][1]*inv0 };
        float2 v1 = { oacc[nt][2]*inv1, oacc[nt][3]*inv1 };
        *(float2*)&op[(size_t)r0*DMODEL + col]       = v0;
        *(float2*)&op[(size_t)(r0+8)*DMODEL + col]   = v1;
    }
}

// ---------------------------------------------------------------------------
// Kernel 5: output projection + valid-token mask (tf32 mma)
// All-invalid blocks write exact zeros and exit.
// ---------------------------------------------------------------------------
__global__ __launch_bounds__(256) void k_gemm_out(
    const float* __restrict__ Wo, const float* __restrict__ bo,
    float* __restrict__ out)
{
    __shared__ float As[128][36];
    __shared__ float Bs[128][36];
    int bm = blockIdx.y * 128;
    int bn = blockIdx.x * 128;
    int tid = threadIdx.x;

    if ((bm & 511) >= g_counts[bm >> 9]) {
        float4 z = {0.f, 0.f, 0.f, 0.f};
        #pragma unroll
        for (int j = 0; j < 16; j++) {
            int id = j*256 + tid;
            int row = id >> 5;
            int col = (id & 31) * 4;
            *(float4*)&out[(size_t)(bm + row)*DMODEL + bn + col] = z;
        }
        return;
    }

    int warp = tid >> 5, lane = tid & 31;
    int wm = warp >> 1, wn = warp & 1;
    int r0 = lane >> 2, c0 = lane & 3;

    float acc[2][8][4];
    #pragma unroll
    for (int mt = 0; mt < 2; mt++)
        #pragma unroll
        for (int nt = 0; nt < 8; nt++)
            #pragma unroll
            for (int r = 0; r < 4; r++) acc[mt][nt][r] = 0.f;

    int lrow = tid >> 3;
    int lcol = (tid & 7) * 4;

    for (int k0 = 0; k0 < DMODEL; k0 += 32) {
        #pragma unroll
        for (int p = 0; p < 4; p++) {
            int row = p*32 + lrow;
            float4 a = *(const float4*)&g_ctx[(size_t)(bm + row)*DMODEL + k0 + lcol];
            float4 w = *(const float4*)&Wo[(size_t)(bn + row)*DMODEL + k0 + lcol];
            As[row][lcol+0] = t32(a.x); As[row][lcol+1] = t32(a.y);
            As[row][lcol+2] = t32(a.z); As[row][lcol+3] = t32(a.w);
            Bs[row][lcol+0] = t32(w.x); Bs[row][lcol+1] = t32(w.y);
            Bs[row][lcol+2] = t32(w.z); Bs[row][lcol+3] = t32(w.w);
        }
        __syncthreads();
        #pragma unroll
        for (int ks = 0; ks < 4; ks++) {
            int kk = ks*8;
            unsigned a[2][4], b[8][2];
            #pragma unroll
            for (int mt = 0; mt < 2; mt++) {
                int mr = wm*32 + mt*16 + r0;
                a[mt][0] = U(As[mr  ][kk + c0]);
                a[mt][1] = U(As[mr+8][kk + c0]);
                a[mt][2] = U(As[mr  ][kk + 4 + c0]);
                a[mt][3] = U(As[mr+8][kk + 4 + c0]);
            }
            #pragma unroll
            for (int nt = 0; nt < 8; nt++) {
                int nr = wn*64 + nt*8 + r0;
                b[nt][0] = U(Bs[nr][kk + c0]);
                b[nt][1] = U(Bs[nr][kk + 4 + c0]);
            }
            #pragma unroll
            for (int mt = 0; mt < 2; mt++)
                #pragma unroll
                for (int nt = 0; nt < 8; nt++)
                    mma8(acc[mt][nt], a[mt], b[nt]);
        }
        __syncthreads();
    }
    #pragma unroll
    for (int mt = 0; mt < 2; mt++) {
        int row = bm + wm*32 + mt*16 + r0;
        int bb0 = (row)     >> 9, tt0 = (row)     & 511;
        int bb1 = (row + 8) >> 9, tt1 = (row + 8) & 511;
        float m0 = (tt0 < g_counts[bb0]) ? 1.f : 0.f;
        float m1 = (tt1 < g_counts[bb1]) ? 1.f : 0.f;
        #pragma unroll
        for (int nt = 0; nt < 8; nt++) {
            int col = bn + wn*64 + nt*8 + 2*c0;
            float bx = bo[col], by = bo[col+1];
            float2 v0 = { (acc[mt][nt][0] + bx)*m0, (acc[mt][nt][1] + by)*m0 };
            float2 v1 = { (acc[mt][nt][2] + bx)*m1, (acc[mt][nt][3] + by)*m1 };
            *(float2*)&out[(size_t)row*DMODEL + col]     = v0;
            *(float2*)&out[(size_t)(row+8)*DMODEL + col] = v1;
        }
    }
}

// ---------------------------------------------------------------------------
extern "C" void kernel_launch(void* const* d_in, const int* in_sizes, int n_in,
                              void* d_out, int out_size)
{
    const float* x     = (const float*)d_in[0];
    const float* invf  = (const float*)d_in[1];
    const float* pastk = (const float*)d_in[2];
    const float* pastv = (const float*)d_in[3];
    const float* Wq    = (const float*)d_in[4];
    const float* bq    = (const float*)d_in[5];
    const float* Wk    = (const float*)d_in[6];
    const float* bk    = (const float*)d_in[7];
    const float* Wv    = (const float*)d_in[8];
    const float* bv    = (const float*)d_in[9];
    const float* Wo    = (const float*)d_in[10];
    const float* bo    = (const float*)d_in[11];
    const int* past_len = (const int*)d_in[13];
    const unsigned char* vmask = (const unsigned char*)d_in[14];
    float* out = (float*)d_out;

    k_setup<<<B_, 32>>>(vmask, past_len, out + OFF_LEN);
    k_gemm_qkv<<<dim3(QKVN/128, MROWS/128), 256>>>(x, Wq, Wk, Wv, bq, bk, bv);
    k_prep<<<dim3(TTOTAL*32/256, B_*H_), 256>>>(pastk, pastv, invf, past_len, out);

    int smem = (3*KVTILE + 64*AT) * 4;   // 69632 bytes -> 3 CTAs/SM
    cudaFuncSetAttribute(k_attn, cudaFuncAttributeMaxDynamicSharedMemorySize, smem);
    k_attn<<<dim3(B_*H_, TNEW/64), 128, smem>>>();

    k_gemm_out<<<dim3(DMODEL/128, MROWS/128), 256>>>(Wo, bo, out);
}

// round 11
// speedup vs baseline: 1.1355x; 1.0369x over previous
#include <cuda_runtime.h>
#include <math.h>

#define B_      8
#define TNEW    512
#define DMODEL  1024
#define H_      16
#define DH      64
#define CACHED  2048
#define TTOTAL  2560
#define MROWS   (B_*TNEW)      // 4096
#define QKVN    3072

#define OFF_K   (MROWS*DMODEL)               // 4194304
#define OFF_V   (OFF_K + B_*H_*TTOTAL*DH)    // 25165824
#define OFF_LEN (OFF_V + B_*H_*TTOTAL*DH)    // 46137344

#define WSZ     (DMODEL*DMODEL)              // 1048576

// Scratch (allocation-free rule: __device__ globals)
__device__ float g_qkv[MROWS*QKVN];        // raw q|k|v projections [4096][3072]
__device__ float g_q  [B_*H_*TNEW*DH];     // roped q (tf32, pre-scaled by 1/8)
__device__ float g_kt [B_*H_*TTOTAL*DH];   // tf32 copy of k_total
__device__ float g_vt [B_*H_*TTOTAL*DH];   // tf32 copy of v_total
__device__ float g_ctx[MROWS*DMODEL];      // attention context (tf32 values)
__device__ float g_xt [MROWS*DMODEL];      // tf32 copy of x_new
__device__ float g_wt [4*WSZ];             // tf32 copies of Wq|Wk|Wv|Wo
__device__ int   g_counts[B_];
__device__ int   g_totals[B_];

// ---------------------------------------------------------------------------
// tf32 / cp.async helpers
// ---------------------------------------------------------------------------
__device__ __forceinline__ float t32(float f) {
    unsigned u;
    asm("cvt.rna.tf32.f32 %0, %1;" : "=r"(u) : "f"(f));
    return __uint_as_float(u);
}
__device__ __forceinline__ unsigned U(float f) { return __float_as_uint(f); }

__device__ __forceinline__ void mma8(float* c, const unsigned* a, const unsigned* b) {
    asm volatile(
        "mma.sync.aligned.m16n8k8.row.col.f32.tf32.tf32.f32 "
        "{%0,%1,%2,%3},{%4,%5,%6,%7},{%8,%9},{%0,%1,%2,%3};"
        : "+f"(c[0]), "+f"(c[1]), "+f"(c[2]), "+f"(c[3])
        : "r"(a[0]), "r"(a[1]), "r"(a[2]), "r"(a[3]), "r"(b[0]), "r"(b[1]));
}

__device__ __forceinline__ void cpa16(float* smem, const float* g) {
    unsigned s = (unsigned)__cvta_generic_to_shared(smem);
    asm volatile("cp.async.cg.shared.global [%0], [%1], 16;" :: "r"(s), "l"(g));
}
__device__ __forceinline__ void cpa_commit() { asm volatile("cp.async.commit_group;"); }
__device__ __forceinline__ void cpa_wait1()  { asm volatile("cp.async.wait_group 1;"); }
__device__ __forceinline__ void cpa_wait0()  { asm volatile("cp.async.wait_group 0;"); }

// ---------------------------------------------------------------------------
// Kernel 0: one-time tf32 pre-conversion of X and W matrices
// ---------------------------------------------------------------------------
__global__ __launch_bounds__(256) void k_cvt(
    const float* __restrict__ X,
    const float* __restrict__ Wq, const float* __restrict__ Wk,
    const float* __restrict__ Wv, const float* __restrict__ Wo)
{
    int idx = blockIdx.x * 256 + threadIdx.x;     // float4 index
    const int XQ = MROWS*DMODEL/4;
    float4 v; float4* dst;
    if (idx < XQ) {
        v = ((const float4*)X)[idx];
        dst = (float4*)g_xt + idx;
    } else {
        int r = idx - XQ;
        int w = r / (WSZ/4);
        int o = r % (WSZ/4);
        const float* src = (w == 0) ? Wq : (w == 1) ? Wk : (w == 2) ? Wv : Wo;
        v = ((const float4*)src)[o];
        dst = (float4*)(g_wt + (size_t)w*WSZ) + o;
    }
    float4 ov = { t32(v.x), t32(v.y), t32(v.z), t32(v.w) };
    *dst = ov;
}

// ---------------------------------------------------------------------------
// Kernel 1: derive new_counts from valid_new_mask (dtype-probed), totals
// ---------------------------------------------------------------------------
__global__ void k_setup(const unsigned char* __restrict__ mask,
                        const int* __restrict__ past_len,
                        float* __restrict__ out_len)
{
    int b = blockIdx.x;
    int lane = threadIdx.x;
    bool bytemode = (mask[7*TNEW + 1] != 0);
    int cnt = 0;
    for (int t = lane; t < TNEW; t += 32) {
        int nz;
        if (bytemode) nz = (mask[b*TNEW + t] != 0);
        else          nz = (((const int*)mask)[b*TNEW + t] != 0);
        cnt += nz;
    }
    #pragma unroll
    for (int o = 16; o; o >>= 1) cnt += __shfl_xor_sync(0xffffffffu, cnt, o);
    if (lane == 0) {
        g_counts[b] = cnt;
        int tot = past_len[b] + cnt;
        g_totals[b] = tot;
        out_len[b] = (float)tot;
    }
}

// ---------------------------------------------------------------------------
// Accurate RoPE angles (fp64 range reduction, fp32 sincos)
// ---------------------------------------------------------------------------
__device__ __forceinline__ void rope_sc(int pos, float fi, float& sn, float& cs)
{
    double f = (double)pos * (double)fi;
    double k = floor(f * 0.15915494309189535);
    float fr = (float)(f - k * 6.283185307179586);
    sincosf(fr, &sn, &cs);
}

// ---------------------------------------------------------------------------
// Shared GEMM body: 128x128 tile, ktile 32, 2-stage cp.async pipeline.
// Inputs are PRE-CONVERTED tf32 -> zero cvt in the loop, raw fragment loads.
// smem: A[2][128][36] then B[2][128][36]
// ---------------------------------------------------------------------------
#define GST 36
#define GSTAGE (128*GST)

__device__ __forceinline__ void gemm_pipe(
    const float* __restrict__ Ag, const float* __restrict__ Bg,
    float* sA, float* sB, int tid, float acc[2][8][4])
{
    int warp = tid >> 5, lane = tid & 31;
    int wm = warp >> 1, wn = warp & 1;
    int r0 = lane >> 2, c0 = lane & 3;
    int lrow = tid >> 3;             // 0..31
    int lcol = (tid & 7) * 4;        // 0,4,...,28

    #pragma unroll
    for (int it = 0; it < 4; it++) {
        int row = it*32 + lrow;
        cpa16(&sA[row*GST + lcol], &Ag[(size_t)row*DMODEL + lcol]);
        cpa16(&sB[row*GST + lcol], &Bg[(size_t)row*DMODEL + lcol]);
    }
    cpa_commit();

    for (int kt = 0; kt < 32; kt++) {
        int st = (kt & 1) * GSTAGE;
        if (kt + 1 < 32) {
            int ns = ((kt + 1) & 1) * GSTAGE;
            int k0 = (kt + 1) * 32;
            #pragma unroll
            for (int it = 0; it < 4; it++) {
                int row = it*32 + lrow;
                cpa16(&sA[ns + row*GST + lcol], &Ag[(size_t)row*DMODEL + k0 + lcol]);
                cpa16(&sB[ns + row*GST + lcol], &Bg[(size_t)row*DMODEL + k0 + lcol]);
            }
            cpa_commit();
            cpa_wait1();
        } else {
            cpa_wait0();
        }
        __syncthreads();

        #pragma unroll
        for (int ks = 0; ks < 4; ks++) {
            int kk = ks*8;
            unsigned a[2][4], b[8][2];
            #pragma unroll
            for (int mt = 0; mt < 2; mt++) {
                int mr = wm*32 + mt*16 + r0;
                a[mt][0] = U(sA[st + (mr    )*GST + kk + c0]);
                a[mt][1] = U(sA[st + (mr + 8)*GST + kk + c0]);
                a[mt][2] = U(sA[st + (mr    )*GST + kk + 4 + c0]);
                a[mt][3] = U(sA[st + (mr + 8)*GST + kk + 4 + c0]);
            }
            #pragma unroll
            for (int nt = 0; nt < 8; nt++) {
                int nr = wn*64 + nt*8 + r0;
                b[nt][0] = U(sB[st + nr*GST + kk + c0]);
                b[nt][1] = U(sB[st + nr*GST + kk + 4 + c0]);
            }
            #pragma unroll
            for (int mt = 0; mt < 2; mt++)
                #pragma unroll
                for (int nt = 0; nt < 8; nt++)
                    mma8(acc[mt][nt], a[mt], b[nt]);
        }
        __syncthreads();
    }
}

// ---------------------------------------------------------------------------
// Kernel 2: QKV projection (pipelined, zero-cvt). Dead-row blocks exit.
// ---------------------------------------------------------------------------
__global__ __launch_bounds__(256) void k_gemm_qkv(
    const float* __restrict__ bq, const float* __restrict__ bk, const float* __restrict__ bv)
{
    extern __shared__ float smem_g[];
    float* sA = smem_g;
    float* sB = smem_g + 2*GSTAGE;

    int bm = blockIdx.y * 128;
    if ((bm & 511) >= g_counts[bm >> 9]) return;

    int bn = blockIdx.x * 128;
    int seg = bn >> 10;
    const float* bias = (seg == 0) ? bq : ((seg == 1) ? bk : bv);
    int nl = bn & 1023;
    int tid = threadIdx.x;
    int warp = tid >> 5, lane = tid & 31;
    int wm = warp >> 1, wn = warp & 1;
    int r0 = lane >> 2, c0 = lane & 3;

    float acc[2][8][4];
    #pragma unroll
    for (int mt = 0; mt < 2; mt++)
        #pragma unroll
        for (int nt = 0; nt < 8; nt++)
            #pragma unroll
            for (int r = 0; r < 4; r++) acc[mt][nt][r] = 0.f;

    gemm_pipe(g_xt + (size_t)bm*DMODEL,
              g_wt + (size_t)seg*WSZ + (size_t)nl*DMODEL,
              sA, sB, tid, acc);

    #pragma unroll
    for (int mt = 0; mt < 2; mt++) {
        #pragma unroll
        for (int nt = 0; nt < 8; nt++) {
            int row = bm + wm*32 + mt*16 + r0;
            int col = bn + wn*64 + nt*8 + 2*c0;
            float bx = bias[col & 1023], by = bias[(col+1) & 1023];
            float2 v0 = { acc[mt][nt][0] + bx, acc[mt][nt][1] + by };
            float2 v1 = { acc[mt][nt][2] + bx, acc[mt][nt][3] + by };
            *(float2*)&g_qkv[(size_t)row*QKVN + col]     = v0;
            *(float2*)&g_qkv[(size_t)(row+8)*QKVN + col] = v1;
        }
    }
}

// ---------------------------------------------------------------------------
// Kernel 3 (fused): assemble k_total/v_total + RoPE on q (tf32, pre-scaled)
// ---------------------------------------------------------------------------
__global__ __launch_bounds__(256) void k_prep(
    const float* __restrict__ pastk, const float* __restrict__ pastv,
    const float* __restrict__ invf, const int* __restrict__ past_len,
    float* __restrict__ out)
{
    int bh = blockIdx.y; int b = bh >> 4; int h = bh & 15;
    int gid = blockIdx.x * 256 + threadIdx.x;
    int i = gid & 31; int s = gid >> 5;
    int pl = past_len[b]; int tot = g_totals[b]; int cnt = g_counts[b];
    float k0, k1, v0, v1;
    if (s < pl) {
        size_t base = ((size_t)bh*CACHED + s) * DH;
        k0 = pastk[base + i]; k1 = pastk[base + i + 32];
        v0 = pastv[base + i]; v1 = pastv[base + i + 32];
    } else if (s < tot) {
        int t = s - pl;
        size_t m = (size_t)(b*TNEW + t) * QKVN;
        float sn, cs; rope_sc(s, invf[i], sn, cs);
        float x0 = g_qkv[m + 1024 + h*DH + i];
        float x1 = g_qkv[m + 1024 + h*DH + i + 32];
        k0 = x0*cs - x1*sn;
        k1 = x1*cs + x0*sn;
        v0 = g_qkv[m + 2048 + h*DH + i];
        v1 = g_qkv[m + 2048 + h*DH + i + 32];
    } else {
        k0 = k1 = v0 = v1 = 0.f;
    }
    size_t base = ((size_t)bh*TTOTAL + s) * DH;
    out[OFF_K + base + i]      = k0;
    out[OFF_K + base + i + 32] = k1;
    out[OFF_V + base + i]      = v0;
    out[OFF_V + base + i + 32] = v1;
    g_kt[base + i]      = t32(k0);
    g_kt[base + i + 32] = t32(k1);
    g_vt[base + i]      = t32(v0);
    g_vt[base + i + 32] = t32(v1);

    if (s < TNEW) {
        int t = s;
        float o0 = 0.f, o1 = 0.f;
        if (t < cnt) {
            int pos = pl + t;
            float sn, cs; rope_sc(pos, invf[i], sn, cs);
            size_t m = (size_t)(b*TNEW + t) * QKVN + h*DH;
            float x0 = g_qkv[m + i];
            float x1 = g_qkv[m + i + 32];
            o0 = t32(x0*cs - x1*sn) * 0.125f;   // exact pow2 fold
            o1 = t32(x1*cs + x0*sn) * 0.125f;
        }
        size_t qb = ((size_t)bh*TNEW + t) * DH;
        g_q[qb + i]      = o0;
        g_q[qb + i + 32] = o1;
    }
}

// ---------------------------------------------------------------------------
// Kernel 4: flash attention (R10 best geometry, unchanged hot loop).
// Epilogue writes t32 values into g_ctx so k_gemm_out loads raw.
// ---------------------------------------------------------------------------
#define AT 68
#define KVTILE (64*AT)

__global__ __launch_bounds__(128, 3) void k_attn()
{
    extern __shared__ float sm[];
    float* Kb[2] = { sm, sm + KVTILE };
    float* Vs = sm + 2*KVTILE;
    float (*Ps)[AT] = (float(*)[AT])(sm + 3*KVTILE);

    int bh = blockIdx.x;
    int b = bh >> 4;
    int qb = blockIdx.y << 6;
    if (qb >= g_counts[b]) return;

    int tid = threadIdx.x;
    int warp = tid >> 5, lane = tid & 31;
    int r0 = lane >> 2, c0 = lane & 3;

    int tot = g_totals[b];
    int nkb = (tot + 63) >> 6;
    const float* kbase = g_kt + (size_t)bh*TTOTAL*DH;
    const float* vbase = g_vt + (size_t)bh*TTOTAL*DH;

    int prow = tid >> 4;
    int pcol = (tid & 15) * 4;

    #pragma unroll
    for (int j = 0; j < 8; j++) {
        int row = j*8 + prow;
        cpa16(&Kb[0][row*AT + pcol], &kbase[(size_t)row*DH + pcol]);
    }
    cpa_commit();

    {
        const float* qp = g_q + ((size_t)bh*TNEW + qb) * DH;
        #pragma unroll
        for (int j = 0; j < 8; j++) {
            int id = j*128 + tid;
            int row = id >> 4;
            int c = (id & 15) * 4;
            *(float4*)&Ps[row][c] = *(const float4*)&qp[(size_t)row*DH + c];
        }
    }
    __syncthreads();

    unsigned qa[8][4];
    int qr = warp*16 + r0;
    #pragma unroll
    for (int ks = 0; ks < 8; ks++) {
        qa[ks][0] = U(Ps[qr  ][ks*8 + c0]);
        qa[ks][1] = U(Ps[qr+8][ks*8 + c0]);
        qa[ks][2] = U(Ps[qr  ][ks*8 + 4 + c0]);
        qa[ks][3] = U(Ps[qr+8][ks*8 + 4 + c0]);
    }

    float oacc[8][4];
    #pragma unroll
    for (int nt = 0; nt < 8; nt++)
        #pragma unroll
        for (int r = 0; r < 4; r++) oacc[nt][r] = 0.f;
    float mrow0 = -1e30f, mrow1 = -1e30f, lrow0 = 0.f, lrow1 = 0.f;

    for (int kb = 0; kb < nkb; kb++) {
        cpa_wait0();
        __syncthreads();

        {
            const float* vg = vbase + (size_t)kb*64*DH;
            #pragma unroll
            for (int j = 0; j < 8; j++) {
                int row = j*8 + prow;
                cpa16(&Vs[row*AT + pcol], &vg[(size_t)row*DH + pcol]);
            }
            cpa_commit();
        }
        bool havek = (kb + 1 < nkb);
        if (havek) {
            int nb = (kb + 1) & 1;
            const float* kg = kbase + (size_t)(kb+1)*64*DH;
            #pragma unroll
            for (int j = 0; j < 8; j++) {
                int row = j*8 + prow;
                cpa16(&Kb[nb][row*AT + pcol], &kg[(size_t)row*DH + pcol]);
            }
            cpa_commit();
        }

        const float* Ks = Kb[kb & 1];

        float sacc[8][4];
        #pragma unroll
        for (int nt = 0; nt < 8; nt++)
            #pragma unroll
            for (int r = 0; r < 4; r++) sacc[nt][r] = 0.f;
        #pragma unroll
        for (int ks = 0; ks < 8; ks++) {
            #pragma unroll
            for (int nt = 0; nt < 8; nt++) {
                unsigned bb[2];
                bb[0] = U(Ks[(nt*8 + r0)*AT + ks*8 + c0]);
                bb[1] = U(Ks[(nt*8 + r0)*AT + ks*8 + 4 + c0]);
                mma8(sacc[nt], qa[ks], bb);
            }
        }

        if (kb == nkb - 1) {
            #pragma unroll
            for (int nt = 0; nt < 8; nt++) {
                int col = kb*64 + nt*8 + 2*c0;
                if (col     >= tot) { sacc[nt][0] = -1e30f; sacc[nt][2] = -1e30f; }
                if (col + 1 >= tot) { sacc[nt][1] = -1e30f; sacc[nt][3] = -1e30f; }
            }
        }

        float ml0 = -1e30f, ml1 = -1e30f;
        #pragma unroll
        for (int nt = 0; nt < 8; nt++) {
            ml0 = fmaxf(ml0, fmaxf(sacc[nt][0], sacc[nt][1]));
            ml1 = fmaxf(ml1, fmaxf(sacc[nt][2], sacc[nt][3]));
        }
        ml0 = fmaxf(ml0, __shfl_xor_sync(0xffffffffu, ml0, 1));
        ml0 = fmaxf(ml0, __shfl_xor_sync(0xffffffffu, ml0, 2));
        ml1 = fmaxf(ml1, __shfl_xor_sync(0xffffffffu, ml1, 1));
        ml1 = fmaxf(ml1, __shfl_xor_sync(0xffffffffu, ml1, 2));

        float mn0 = fmaxf(mrow0, ml0), mn1 = fmaxf(mrow1, ml1);
        float e0 = __expf(mrow0 - mn0), e1 = __expf(mrow1 - mn1);
        mrow0 = mn0; mrow1 = mn1;

        float ls0 = 0.f, ls1 = 0.f;
        #pragma unroll
        for (int nt = 0; nt < 8; nt++) {
            float p0 = __expf(sacc[nt][0] - mn0);
            float p1 = __expf(sacc[nt][1] - mn0);
            float p2 = __expf(sacc[nt][2] - mn1);
            float p3 = __expf(sacc[nt][3] - mn1);
            ls0 += p0 + p1; ls1 += p2 + p3;
            float2 w0 = { t32(p0), t32(p1) };
            float2 w1 = { t32(p2), t32(p3) };
            *(float2*)&Ps[warp*16 + r0    ][nt*8 + 2*c0] = w0;
            *(float2*)&Ps[warp*16 + r0 + 8][nt*8 + 2*c0] = w1;
            oacc[nt][0] *= e0; oacc[nt][1] *= e0;
            oacc[nt][2] *= e1; oacc[nt][3] *= e1;
        }
        ls0 += __shfl_xor_sync(0xffffffffu, ls0, 1);
        ls0 += __shfl_xor_sync(0xffffffffu, ls0, 2);
        ls1 += __shfl_xor_sync(0xffffffffu, ls1, 1);
        ls1 += __shfl_xor_sync(0xffffffffu, ls1, 2);
        lrow0 = lrow0*e0 + ls0;
        lrow1 = lrow1*e1 + ls1;

        if (havek) cpa_wait1(); else cpa_wait0();
        __syncthreads();

        #pragma unroll
        for (int ks = 0; ks < 8; ks++) {
            unsigned pa[4];
            pa[0] = U(Ps[warp*16 + r0    ][ks*8 + c0]);
            pa[1] = U(Ps[warp*16 + r0 + 8][ks*8 + c0]);
            pa[2] = U(Ps[warp*16 + r0    ][ks*8 + 4 + c0]);
            pa[3] = U(Ps[warp*16 + r0 + 8][ks*8 + 4 + c0]);
            #pragma unroll
            for (int nt = 0; nt < 8; nt++) {
                unsigned bb[2];
                bb[0] = U(Vs[(ks*8 + c0    )*AT + nt*8 + r0]);
                bb[1] = U(Vs[(ks*8 + 4 + c0)*AT + nt*8 + r0]);
                mma8(oacc[nt], pa, bb);
            }
        }
    }

    // finalize: write tf32 values (k_gemm_out loads raw -> same bits as before)
    float inv0 = 1.f / lrow0, inv1 = 1.f / lrow1;
    float* op = g_ctx + ((size_t)b*TNEW + qb + warp*16) * DMODEL + (bh & 15)*DH;
    #pragma unroll
    for (int nt = 0; nt < 8; nt++) {
        int col = nt*8 + 2*c0;
        float2 v0 = { t32(oacc[nt][0]*inv0), t32(oacc[nt][1]*inv0) };
        float2 v1 = { t32(oacc[nt][2]*inv1), t32(oacc[nt][3]*inv1) };
        *(float2*)&op[(size_t)r0*DMODEL + col]       = v0;
        *(float2*)&op[(size_t)(r0+8)*DMODEL + col]   = v1;
    }
}

// ---------------------------------------------------------------------------
// Kernel 5: output projection (pipelined, zero-cvt) + valid-token mask.
// All-invalid blocks write exact zeros and exit.
// ---------------------------------------------------------------------------
__global__ __launch_bounds__(256) void k_gemm_out(
    const float* __restrict__ bo, float* __restrict__ out)
{
    extern __shared__ float smem_g[];
    float* sA = smem_g;
    float* sB = smem_g + 2*GSTAGE;

    int bm = blockIdx.y * 128;
    int bn = blockIdx.x * 128;
    int tid = threadIdx.x;

    if ((bm & 511) >= g_counts[bm >> 9]) {
        float4 z = {0.f, 0.f, 0.f, 0.f};
        #pragma unroll
        for (int j = 0; j < 16; j++) {
            int id = j*256 + tid;
            int row = id >> 5;
            int col = (id & 31) * 4;
            *(float4*)&out[(size_t)(bm + row)*DMODEL + bn + col] = z;
        }
        return;
    }

    int warp = tid >> 5, lane = tid & 31;
    int wm = warp >> 1, wn = warp & 1;
    int r0 = lane >> 2, c0 = lane & 3;

    float acc[2][8][4];
    #pragma unroll
    for (int mt = 0; mt < 2; mt++)
        #pragma unroll
        for (int nt = 0; nt < 8; nt++)
            #pragma unroll
            for (int r = 0; r < 4; r++) acc[mt][nt][r] = 0.f;

    gemm_pipe(g_ctx + (size_t)bm*DMODEL,
              g_wt + (size_t)3*WSZ + (size_t)bn*DMODEL,
              sA, sB, tid, acc);

    #pragma unroll
    for (int mt = 0; mt < 2; mt++) {
        int row = bm + wm*32 + mt*16 + r0;
        int bb0 = (row)     >> 9, tt0 = (row)     & 511;
        int bb1 = (row + 8) >> 9, tt1 = (row + 8) & 511;
        float m0 = (tt0 < g_counts[bb0]) ? 1.f : 0.f;
        float m1 = (tt1 < g_counts[bb1]) ? 1.f : 0.f;
        #pragma unroll
        for (int nt = 0; nt < 8; nt++) {
            int col = bn + wn*64 + nt*8 + 2*c0;
            float bx = bo[col], by = bo[col+1];
            float2 v0 = { (acc[mt][nt][0] + bx)*m0, (acc[mt][nt][1] + by)*m0 };
            float2 v1 = { (acc[mt][nt][2] + bx)*m1, (acc[mt][nt][3] + by)*m1 };
            *(float2*)&out[(size_t)row*DMODEL + col]     = v0;
            *(float2*)&out[(size_t)(row+8)*DMODEL + col] = v1;
        }
    }
}

// ---------------------------------------------------------------------------
extern "C" void kernel_launch(void* const* d_in, const int* in_sizes, int n_in,
                              void* d_out, int out_size)
{
    const float* x     = (const float*)d_in[0];
    const float* invf  = (const float*)d_in[1];
    const float* pastk = (const float*)d_in[2];
    const float* pastv = (const float*)d_in[3];
    const float* Wq    = (const float*)d_in[4];
    const float* bq    = (const float*)d_in[5];
    const float* Wk    = (const float*)d_in[6];
    const float* bk    = (const float*)d_in[7];
    const float* Wv    = (const float*)d_in[8];
    const float* bv    = (const float*)d_in[9];
    const float* Wo    = (const float*)d_in[10];
    const float* bo    = (const float*)d_in[11];
    const int* past_len = (const int*)d_in[13];
    const unsigned char* vmask = (const unsigned char*)d_in[14];
    float* out = (float*)d_out;

    int gsmem = 4*GSTAGE*4;  // 73728 B
    cudaFuncSetAttribute(k_gemm_qkv, cudaFuncAttributeMaxDynamicSharedMemorySize, gsmem);
    cudaFuncSetAttribute(k_gemm_out, cudaFuncAttributeMaxDynamicSharedMemorySize, gsmem);

    k_setup<<<B_, 32>>>(vmask, past_len, out + OFF_LEN);
    k_cvt<<<(MROWS*DMODEL + 4*WSZ)/4/256, 256>>>(x, Wq, Wk, Wv, Wo);
    k_gemm_qkv<<<dim3(QKVN/128, MROWS/128), 256, gsmem>>>(bq, bk, bv);
    k_prep<<<dim3(TTOTAL*32/256, B_*H_), 256>>>(pastk, pastv, invf, past_len, out);

    int smem = (3*KVTILE + 64*AT) * 4;   // 69632 -> 3 CTAs/SM
    cudaFuncSetAttribute(k_attn, cudaFuncAttributeMaxDynamicSharedMemorySize, smem);
    k_attn<<<dim3(B_*H_, TNEW/64), 128, smem>>>();

    k_gemm_out<<<dim3(DMODEL/128, MROWS/128), 256, gsmem>>>(bo, out);
}